// round 7
// baseline (speedup 1.0000x reference)
#include <cuda_runtime.h>
#include <cuda_bf16.h>

#define N_WAVES 128
#define W_MUFU 70        // waves via MUFU.SIN; remaining 58 via FMA-pipe minimax poly
#define TPB 128
#define PPT 4            // points per thread = 2 packed pairs

typedef unsigned long long u64;

__device__ __forceinline__ u64 pk(float lo, float hi) {
    u64 r; asm("mov.b64 %0, {%1, %2};" : "=l"(r) : "f"(lo), "f"(hi)); return r;
}
__device__ __forceinline__ void upk(u64 v, float& lo, float& hi) {
    asm("mov.b64 {%0, %1}, %2;" : "=f"(lo), "=f"(hi) : "l"(v));
}
__device__ __forceinline__ u64 pk32(unsigned lo, unsigned hi) {
    u64 r; asm("mov.b64 %0, {%1, %2};" : "=l"(r) : "r"(lo), "r"(hi)); return r;
}
__device__ __forceinline__ void upk32(u64 v, unsigned& lo, unsigned& hi) {
    asm("mov.b64 {%0, %1}, %2;" : "=r"(lo), "=r"(hi) : "l"(v));
}
__device__ __forceinline__ u64 fma2(u64 a, u64 b, u64 c) {
    u64 d; asm("fma.rn.f32x2 %0, %1, %2, %3;" : "=l"(d) : "l"(a), "l"(b), "l"(c)); return d;
}
__device__ __forceinline__ u64 mul2(u64 a, u64 b) {
    u64 d; asm("mul.rn.f32x2 %0, %1, %2;" : "=l"(d) : "l"(a), "l"(b)); return d;
}
__device__ __forceinline__ u64 add2(u64 a, u64 b) {
    u64 d; asm("add.rn.f32x2 %0, %1, %2;" : "=l"(d) : "l"(a), "l"(b)); return d;
}
__device__ __forceinline__ u64 sub2(u64 a, u64 b) {
    u64 d; asm("sub.rn.f32x2 %0, %1, %2;" : "=l"(d) : "l"(a), "l"(b)); return d;
}
__device__ __forceinline__ float sinap(float a) {
    float r; asm("sin.approx.f32 %0, %1;" : "=f"(r) : "f"(a)); return r;
}

// sin(pi*d), d in [-0.5, 0.5]: degree-7 odd minimax, coeffs folded to d-domain
#define A1F  3.14158197f
#define A3F -5.16714000f
#define A5F  2.54189000f
#define A7F -0.55461700f

__global__ void __launch_bounds__(TPB, 8)
wave_kernel(const float4* __restrict__ x4,   // 2 points per float4
            const float* __restrict__ freqs,
            const float* __restrict__ rots,
            const float* __restrict__ coeffs,
            float2* __restrict__ out2, int n) {
    // MUFU waves (w < W_MUFU): params in cycles.
    // Poly waves: params PRE-DOUBLED (half-cycle domain v = 2u).
    // swp[2w] = {(gx,gx),(gy,gy)}, swp[2w+1] = {(ph,ph),(A,A)}
    __shared__ ulonglong2 swp[2 * N_WAVES];
    if (threadIdx.x < N_WAVES) {
        int w = threadIdx.x;
        float f  = freqs[w];
        float r  = rots[w];
        float c0 = coeffs[2 * w];
        float c1 = coeffs[2 * w + 1];
        float sr, cr;
        sincosf(r, &sr, &cr);
        float A  = sqrtf(c0 * c0 + c1 * c1);
        float ph = atan2f(c1, c0) * 0.15915494309189535f;  // cycles
        float gx = f * cr, gy = f * sr;
        if (w >= W_MUFU) { gx *= 2.f; gy *= 2.f; ph *= 2.f; }  // half-cycle domain
        ulonglong2 q0, q1;
        q0.x = pk(gx, gx); q0.y = pk(gy, gy);
        q1.x = pk(ph, ph); q1.y = pk(A, A);
        swp[2 * w]     = q0;
        swp[2 * w + 1] = q1;
    }
    __syncthreads();

    int pairsTotal = n >> 1;
    int pA = blockIdx.x * (2 * TPB) + threadIdx.x;   // float4 index, pair 1
    int pB = pA + TPB;                               // float4 index, pair 2

    float4 a = (pA < pairsTotal) ? x4[pA] : make_float4(0.f, 0.f, 0.f, 0.f);
    float4 b = (pB < pairsTotal) ? x4[pB] : make_float4(0.f, 0.f, 0.f, 0.f);
    u64 pxA = pk(a.x, a.z), pyA = pk(a.y, a.w);
    u64 pxB = pk(b.x, b.z), pyB = pk(b.y, b.w);
    u64 accA = pk(0.f, 0.f), accB = pk(0.f, 0.f);

    const u64 MAG   = pk(12582912.f, 12582912.f);    // 1.5 * 2^23
    const u64 TWOPI = pk(6.283185307179586f, 6.283185307179586f);
    const u64 PA1 = pk(A1F, A1F), PA3 = pk(A3F, A3F);
    const u64 PA5 = pk(A5F, A5F), PA7 = pk(A7F, A7F);

    // ---- MUFU-path waves (cycle domain, exact range reduce, MUFU.SIN) ----
#pragma unroll 2
    for (int w = 0; w < W_MUFU; w++) {
        ulonglong2 q0 = swp[2 * w];
        ulonglong2 q1 = swp[2 * w + 1];
        // pair A
        u64 uA = fma2(pxA, q0.x, fma2(pyA, q0.y, q1.x));
        u64 tA = add2(uA, MAG);
        u64 nA = sub2(tA, MAG);
        u64 dA = sub2(uA, nA);
        u64 rA = mul2(dA, TWOPI);
        // pair B (interleaved: 4 independent sins in flight)
        u64 uB = fma2(pxB, q0.x, fma2(pyB, q0.y, q1.x));
        u64 tB = add2(uB, MAG);
        u64 nB = sub2(tB, MAG);
        u64 dB = sub2(uB, nB);
        u64 rB = mul2(dB, TWOPI);
        float ra0, ra1, rb0, rb1;
        upk(rA, ra0, ra1); upk(rB, rb0, rb1);
        u64 sA = pk(sinap(ra0), sinap(ra1));
        u64 sB = pk(sinap(rb0), sinap(rb1));
        accA = fma2(q1.y, sA, accA);
        accB = fma2(q1.y, sB, accB);
    }

    // ---- polynomial-path waves (half-cycle domain, FMA pipe) ----
#pragma unroll 2
    for (int w = W_MUFU; w < N_WAVES; w++) {
        ulonglong2 q0 = swp[2 * w];
        ulonglong2 q1 = swp[2 * w + 1];
        {   // pair A
            u64 v = fma2(pxA, q0.x, fma2(pyA, q0.y, q1.x));
            u64 t = add2(v, MAG);             // mantissa bit0 = parity of rint(v)
            u64 nn = sub2(t, MAG);
            u64 d = sub2(v, nn);              // [-0.5, 0.5]
            u64 s = mul2(d, d);
            u64 pl = fma2(PA7, s, PA5);
            pl = fma2(pl, s, PA3);
            pl = fma2(pl, s, PA1);
            u64 r = mul2(pl, d);              // sin(pi*d)
            unsigned tl, th, rl, rh;
            upk32(t, tl, th); upk32(r, rl, rh);
            rl ^= (tl << 31); rh ^= (th << 31);   // * (-1)^rint(v)
            accA = fma2(q1.y, pk32(rl, rh), accA);
        }
        {   // pair B
            u64 v = fma2(pxB, q0.x, fma2(pyB, q0.y, q1.x));
            u64 t = add2(v, MAG);
            u64 nn = sub2(t, MAG);
            u64 d = sub2(v, nn);
            u64 s = mul2(d, d);
            u64 pl = fma2(PA7, s, PA5);
            pl = fma2(pl, s, PA3);
            pl = fma2(pl, s, PA1);
            u64 r = mul2(pl, d);
            unsigned tl, th, rl, rh;
            upk32(t, tl, th); upk32(r, rl, rh);
            rl ^= (tl << 31); rh ^= (th << 31);
            accB = fma2(q1.y, pk32(rl, rh), accB);
        }
    }

    float o0, o1;
    if (pA < pairsTotal) { upk(accA, o0, o1); out2[pA] = make_float2(o0, o1); }
    if (pB < pairsTotal) { upk(accB, o0, o1); out2[pB] = make_float2(o0, o1); }

    // Odd-n tail: single scalar point via cycle-domain MUFU path.
    if ((n & 1) && blockIdx.x == 0 && threadIdx.x == 0) {
        float tx = ((const float2*)x4)[n - 1].x;
        float ty = ((const float2*)x4)[n - 1].y;
        float ac = 0.f;
        for (int w = 0; w < N_WAVES; w++) {
            float gx, gxd, gy, gyd, ph, phd, A, Ad;
            upk(swp[2 * w].x, gx, gxd);
            upk(swp[2 * w].y, gy, gyd);
            upk(swp[2 * w + 1].x, ph, phd);
            upk(swp[2 * w + 1].y, A, Ad);
            float sc = (w >= W_MUFU) ? 0.5f : 1.0f;    // undo pre-doubling
            float u = fmaf(tx, gx * sc, fmaf(ty, gy * sc, ph * sc));
            float d = u - rintf(u);
            ac = fmaf(A, sinap(6.283185307179586f * d), ac);
        }
        ((float*)out2)[n - 1] = ac;
    }
}

extern "C" void kernel_launch(void* const* d_in, const int* in_sizes, int n_in,
                              void* d_out, int out_size) {
    const float* x      = (const float*)d_in[0];  // [N,2]
    const float* freqs  = (const float*)d_in[1];  // [W,1]
    const float* rots   = (const float*)d_in[2];  // [W,1]
    const float* coeffs = (const float*)d_in[3];  // [W,2]
    float* out = (float*)d_out;                   // [N,1]

    int n = in_sizes[0] / 2;

    int pairs = (n + 1) / 2;
    int blocks = (pairs + 2 * TPB - 1) / (2 * TPB);
    wave_kernel<<<blocks, TPB>>>((const float4*)x, freqs, rots, coeffs,
                                 (float2*)out, n);
}